// round 1
// baseline (speedup 1.0000x reference)
#include <cuda_runtime.h>
#include <cstddef>

#define BATCH 8
#define SEQ   2048
#define EMB   1024
#define MTOT  (BATCH * SEQ)

// ---------------- scratch (device globals; no runtime allocation) ----------------
__device__ float g_q[(size_t)MTOT * EMB];              // 64 MB
__device__ float g_k[(size_t)MTOT * EMB];              // 64 MB
__device__ float g_v[(size_t)MTOT * EMB];              // 64 MB
__device__ float g_p[(size_t)BATCH * SEQ * SEQ];       // 128 MB

// =====================================================================
// Kernel 1: C[m,n] = sum_k A[m,k] * B[n,k] + bias[n]   ("NT" gemm)
// A: [M,K] row-major, B: [N,K] row-major. 128x128x8 tile, 8x8 per thread.
// =====================================================================
__global__ __launch_bounds__(256) void gemm_nt_bias(
    const float* __restrict__ A,
    const float* __restrict__ B,
    const float* __restrict__ bias,
    float* __restrict__ C,
    int M, int N, int K)
{
    constexpr int BM = 128, BN = 128, BK = 8;
    __shared__ __align__(16) float As[BK][BM];
    __shared__ __align__(16) float Bs[BK][BN];

    const int bm = blockIdx.y * BM;
    const int bn = blockIdx.x * BN;
    const int tid = threadIdx.x;

    const int lr = tid >> 1;          // 0..127
    const int lc = (tid & 1) * 4;     // 0 or 4
    const int tr = (tid >> 4) * 8;    // 0..120
    const int tc = (tid & 15) * 8;    // 0..120

    float acc[8][8];
#pragma unroll
    for (int i = 0; i < 8; i++)
#pragma unroll
        for (int j = 0; j < 8; j++) acc[i][j] = 0.0f;

    for (int k0 = 0; k0 < K; k0 += BK) {
        float4 a4 = *(const float4*)(A + (size_t)(bm + lr) * K + k0 + lc);
        float4 b4 = *(const float4*)(B + (size_t)(bn + lr) * K + k0 + lc);
        As[lc + 0][lr] = a4.x; As[lc + 1][lr] = a4.y;
        As[lc + 2][lr] = a4.z; As[lc + 3][lr] = a4.w;
        Bs[lc + 0][lr] = b4.x; Bs[lc + 1][lr] = b4.y;
        Bs[lc + 2][lr] = b4.z; Bs[lc + 3][lr] = b4.w;
        __syncthreads();

#pragma unroll
        for (int k = 0; k < BK; k++) {
            float ar[8], br[8];
#pragma unroll
            for (int i = 0; i < 8; i += 4) {
                *(float4*)&ar[i] = *(const float4*)&As[k][tr + i];
                *(float4*)&br[i] = *(const float4*)&Bs[k][tc + i];
            }
#pragma unroll
            for (int i = 0; i < 8; i++)
#pragma unroll
                for (int j = 0; j < 8; j++)
                    acc[i][j] += ar[i] * br[j];
        }
        __syncthreads();
    }

#pragma unroll
    for (int i = 0; i < 8; i++) {
#pragma unroll
        for (int j = 0; j < 8; j += 4) {
            float4 o;
            o.x = acc[i][j + 0] + bias[bn + tc + j + 0];
            o.y = acc[i][j + 1] + bias[bn + tc + j + 1];
            o.z = acc[i][j + 2] + bias[bn + tc + j + 2];
            o.w = acc[i][j + 3] + bias[bn + tc + j + 3];
            *(float4*)(C + (size_t)(bm + tr + i) * N + bn + tc + j) = o;
        }
    }
}

// =====================================================================
// Kernel 2: per-batch P[i,j] = scale * sum_e Q[i,e] * K[j,e]
// Skips blocks fully above the causal diagonal.
// =====================================================================
__global__ __launch_bounds__(256) void gemm_qk(
    const float* __restrict__ Qg,
    const float* __restrict__ Kg,
    float* __restrict__ Pg,
    float scale)
{
    constexpr int BM = 128, BN = 128, BK = 8;
    const int bm = blockIdx.y * BM;
    const int bn = blockIdx.x * BN;
    if (bn > bm + BM - 1) return;   // entirely masked

    __shared__ __align__(16) float As[BK][BM];
    __shared__ __align__(16) float Bs[BK][BN];

    const int b = blockIdx.z;
    const float* A = Qg + (size_t)b * SEQ * EMB;
    const float* B = Kg + (size_t)b * SEQ * EMB;
    float* C = Pg + (size_t)b * SEQ * SEQ;

    const int tid = threadIdx.x;
    const int lr = tid >> 1;
    const int lc = (tid & 1) * 4;
    const int tr = (tid >> 4) * 8;
    const int tc = (tid & 15) * 8;

    float acc[8][8];
#pragma unroll
    for (int i = 0; i < 8; i++)
#pragma unroll
        for (int j = 0; j < 8; j++) acc[i][j] = 0.0f;

    for (int k0 = 0; k0 < EMB; k0 += BK) {
        float4 a4 = *(const float4*)(A + (size_t)(bm + lr) * EMB + k0 + lc);
        float4 b4 = *(const float4*)(B + (size_t)(bn + lr) * EMB + k0 + lc);
        As[lc + 0][lr] = a4.x; As[lc + 1][lr] = a4.y;
        As[lc + 2][lr] = a4.z; As[lc + 3][lr] = a4.w;
        Bs[lc + 0][lr] = b4.x; Bs[lc + 1][lr] = b4.y;
        Bs[lc + 2][lr] = b4.z; Bs[lc + 3][lr] = b4.w;
        __syncthreads();

#pragma unroll
        for (int k = 0; k < BK; k++) {
            float ar[8], br[8];
#pragma unroll
            for (int i = 0; i < 8; i += 4) {
                *(float4*)&ar[i] = *(const float4*)&As[k][tr + i];
                *(float4*)&br[i] = *(const float4*)&Bs[k][tc + i];
            }
#pragma unroll
            for (int i = 0; i < 8; i++)
#pragma unroll
                for (int j = 0; j < 8; j++)
                    acc[i][j] += ar[i] * br[j];
        }
        __syncthreads();
    }

#pragma unroll
    for (int i = 0; i < 8; i++) {
#pragma unroll
        for (int j = 0; j < 8; j += 4) {
            float4 o;
            o.x = acc[i][j + 0] * scale;
            o.y = acc[i][j + 1] * scale;
            o.z = acc[i][j + 2] * scale;
            o.w = acc[i][j + 3] * scale;
            *(float4*)(C + (size_t)(bm + tr + i) * SEQ + bn + tc + j) = o;
        }
    }
}

// =====================================================================
// Kernel 3: causal softmax in place on P. One CTA (256 thr) per row.
// Reads only j <= i; writes zeros for j > i (so PV needs no mask).
// =====================================================================
__global__ __launch_bounds__(256) void softmax_causal(float* __restrict__ Pg)
{
    const int i = blockIdx.x;
    const int b = blockIdx.y;
    float* row = Pg + ((size_t)b * SEQ + i) * SEQ;
    const int len = i + 1;

    __shared__ float buf[SEQ];
    __shared__ float red[8];
    __shared__ float sval;

    const int tid = threadIdx.x;
    const int lane = tid & 31;
    const int warp = tid >> 5;

    // ---- pass 1: load + max ----
    float m = -1e30f;
    for (int j = tid; j < len; j += 256) {
        float v = row[j];
        buf[j] = v;
        m = fmaxf(m, v);
    }
#pragma unroll
    for (int o = 16; o > 0; o >>= 1) m = fmaxf(m, __shfl_xor_sync(0xffffffffu, m, o));
    if (lane == 0) red[warp] = m;
    __syncthreads();
    if (tid == 0) {
        float mm = red[0];
#pragma unroll
        for (int w = 1; w < 8; w++) mm = fmaxf(mm, red[w]);
        sval = mm;
    }
    __syncthreads();
    const float rowmax = sval;
    __syncthreads();

    // ---- pass 2: exp + sum ----
    float s = 0.0f;
    for (int j = tid; j < len; j += 256) {
        float e = __expf(buf[j] - rowmax);
        buf[j] = e;
        s += e;
    }
#pragma unroll
    for (int o = 16; o > 0; o >>= 1) s += __shfl_xor_sync(0xffffffffu, s, o);
    if (lane == 0) red[warp] = s;
    __syncthreads();
    if (tid == 0) {
        float ss = red[0];
#pragma unroll
        for (int w = 1; w < 8; w++) ss += red[w];
        sval = 1.0f / ss;
    }
    __syncthreads();
    const float inv = sval;

    // ---- pass 3: write normalized + zero tail ----
    for (int j = tid; j < len; j += 256) row[j] = buf[j] * inv;
    for (int j = len + tid; j < SEQ; j += 256) row[j] = 0.0f;
}

// =====================================================================
// Kernel 4: per-batch O[i,e] = sum_j P[i,j] * V[j,e]   ("NN" gemm)
// k-loop truncated at the diagonal block (P[i,j]=0 for j>i).
// =====================================================================
__global__ __launch_bounds__(256) void gemm_pv(
    const float* __restrict__ Pg,
    const float* __restrict__ Vg,
    float* __restrict__ Og)
{
    constexpr int BM = 128, BN = 128, BK = 8;
    __shared__ __align__(16) float As[BK][BM];
    __shared__ __align__(16) float Bs[BK][BN];

    const int b = blockIdx.z;
    const float* A = Pg + (size_t)b * SEQ * SEQ;
    const float* B = Vg + (size_t)b * SEQ * EMB;
    float* C = Og + (size_t)b * SEQ * EMB;

    const int bm = blockIdx.y * BM;
    const int bn = blockIdx.x * BN;
    const int tid = threadIdx.x;

    const int lr = tid >> 1;          // A tile row
    const int lc = (tid & 1) * 4;     // A tile col group
    const int vr = tid >> 5;          // V tile row (0..7)
    const int vc = (tid & 31) * 4;    // V tile col group
    const int tr = (tid >> 4) * 8;
    const int tc = (tid & 15) * 8;

    float acc[8][8];
#pragma unroll
    for (int i = 0; i < 8; i++)
#pragma unroll
        for (int j = 0; j < 8; j++) acc[i][j] = 0.0f;

    const int kend = bm + BM;  // causal truncation
    for (int k0 = 0; k0 < kend; k0 += BK) {
        float4 a4 = *(const float4*)(A + (size_t)(bm + lr) * SEQ + k0 + lc);
        As[lc + 0][lr] = a4.x; As[lc + 1][lr] = a4.y;
        As[lc + 2][lr] = a4.z; As[lc + 3][lr] = a4.w;
        *(float4*)&Bs[vr][vc] =
            *(const float4*)(B + (size_t)(k0 + vr) * EMB + bn + vc);
        __syncthreads();

#pragma unroll
        for (int k = 0; k < BK; k++) {
            float ar[8], br[8];
#pragma unroll
            for (int i = 0; i < 8; i += 4) {
                *(float4*)&ar[i] = *(const float4*)&As[k][tr + i];
                *(float4*)&br[i] = *(const float4*)&Bs[k][tc + i];
            }
#pragma unroll
            for (int i = 0; i < 8; i++)
#pragma unroll
                for (int j = 0; j < 8; j++)
                    acc[i][j] += ar[i] * br[j];
        }
        __syncthreads();
    }

#pragma unroll
    for (int i = 0; i < 8; i++) {
#pragma unroll
        for (int j = 0; j < 8; j += 4) {
            float4 o;
            o.x = acc[i][j + 0]; o.y = acc[i][j + 1];
            o.z = acc[i][j + 2]; o.w = acc[i][j + 3];
            *(float4*)(C + (size_t)(bm + tr + i) * EMB + bn + tc + j) = o;
        }
    }
}

// =====================================================================
// launch
// =====================================================================
extern "C" void kernel_launch(void* const* d_in, const int* in_sizes, int n_in,
                              void* d_out, int out_size)
{
    const float* x  = (const float*)d_in[0];
    const float* Wq = (const float*)d_in[1];
    const float* bq = (const float*)d_in[2];
    const float* Wk = (const float*)d_in[3];
    const float* bk = (const float*)d_in[4];
    const float* Wv = (const float*)d_in[5];
    const float* bv = (const float*)d_in[6];
    float* out = (float*)d_out;

    float* q; cudaGetSymbolAddress((void**)&q, g_q);
    float* k; cudaGetSymbolAddress((void**)&k, g_k);
    float* v; cudaGetSymbolAddress((void**)&v, g_v);
    float* p; cudaGetSymbolAddress((void**)&p, g_p);

    // 1) QKV projections
    dim3 gQKV(EMB / 128, MTOT / 128, 1);
    gemm_nt_bias<<<gQKV, 256>>>(x, Wq, bq, q, MTOT, EMB, EMB);
    gemm_nt_bias<<<gQKV, 256>>>(x, Wk, bk, k, MTOT, EMB, EMB);
    gemm_nt_bias<<<gQKV, 256>>>(x, Wv, bv, v, MTOT, EMB, EMB);

    // 2) scaled QK^T with causal block skipping
    const float scale = 1.0f / 32.0f;  // 1/sqrt(1024)
    dim3 gQK(SEQ / 128, SEQ / 128, BATCH);
    gemm_qk<<<gQK, 256>>>(q, k, p, scale);

    // 3) causal softmax (writes zeros above diagonal)
    dim3 gSM(SEQ, BATCH, 1);
    softmax_causal<<<gSM, 256>>>(p);

    // 4) PV
    dim3 gPV(EMB / 128, SEQ / 128, BATCH);
    gemm_pv<<<gPV, 256>>>(p, v, out);
}

// round 2
// speedup vs baseline: 3.8837x; 3.8837x over previous
#include <cuda_runtime.h>
#include <cstddef>

#define BATCH 8
#define SEQ   2048
#define EMB   1024
#define MTOT  (BATCH * SEQ)

// ---------------- scratch (device globals; no runtime allocation) ----------------
__device__ float g_q[(size_t)MTOT * EMB];              // 64 MB
__device__ float g_k[(size_t)MTOT * EMB];              // 64 MB
__device__ float g_v[(size_t)MTOT * EMB];              // 64 MB (holds Vt: [b][e][s])
__device__ float g_p[(size_t)BATCH * SEQ * SEQ];       // 128 MB

// ---------------- helpers ----------------
__device__ __forceinline__ unsigned f2tf(float f) {
    unsigned u;
    asm("cvt.rna.tf32.f32 %0, %1;" : "=r"(u) : "f"(f));
    return u;
}

__device__ __forceinline__ void mma_tf32(float c[4], const unsigned a[4], const unsigned b[2]) {
    asm volatile(
        "mma.sync.aligned.m16n8k8.row.col.f32.tf32.tf32.f32 "
        "{%0,%1,%2,%3}, {%4,%5,%6,%7}, {%8,%9}, {%0,%1,%2,%3};\n"
        : "+f"(c[0]), "+f"(c[1]), "+f"(c[2]), "+f"(c[3])
        : "r"(a[0]), "r"(a[1]), "r"(a[2]), "r"(a[3]), "r"(b[0]), "r"(b[1]));
}

// =====================================================================
// Unified NT tensor-core GEMM: C[m,n] = sum_k A[m,k] * B[n,k] (+bias)(*scale)
//   MODE 0: projection, C row-major [M,N], +bias
//   MODE 1: projection, C transposed per batch -> Vt[b][n][s], +bias
//   MODE 2: QK^T per batch (blockIdx.z), *scale, causal block skip
//   MODE 3: PV per batch, k-loop truncated at diagonal
// A rows length K, B rows length K (both row-major over k). 128x128x32 tile.
// =====================================================================
template <int MODE>
__global__ __launch_bounds__(256) void mma_gemm(
    const float* __restrict__ Ag,
    const float* __restrict__ Bg,
    const float* __restrict__ bias,
    float* __restrict__ Cg,
    int M, int N, int K, float scale)
{
    constexpr int BM = 128, BN = 128, BK = 32, LDS = 36;  // stride 36: conflict-free frags
    __shared__ unsigned As[BM * LDS];
    __shared__ unsigned Bs[BN * LDS];

    const int bm = blockIdx.y * BM;
    const int bn = blockIdx.x * BN;
    if (MODE == 2 && blockIdx.x > blockIdx.y) return;  // block fully above causal diag

    const int b = (MODE >= 2) ? blockIdx.z : 0;
    const float* A = Ag + (size_t)b * M * K;
    const float* B = Bg + (size_t)b * N * K;

    const int tid  = threadIdx.x;
    const int lane = tid & 31;
    const int wid  = tid >> 5;
    const int gr   = lane >> 2;      // 0..7
    const int gc   = lane & 3;       // 0..3
    const int wm0  = (wid >> 2) * 64;  // warp row origin in tile
    const int wn0  = (wid & 3) * 32;   // warp col origin in tile

    // G2S mapping: each thread loads 16 floats of one 32-float row
    const int r   = tid >> 1;
    const int cg  = (tid & 1) * 16;

    float acc[4][4][4];
#pragma unroll
    for (int i = 0; i < 4; i++)
#pragma unroll
        for (int j = 0; j < 4; j++)
#pragma unroll
            for (int t = 0; t < 4; t++) acc[i][j][t] = 0.0f;

    const int kend = (MODE == 3) ? (bm + BM) : K;  // causal truncation for PV

    for (int k0 = 0; k0 < kend; k0 += BK) {
        // ---- G2S with tf32 rounding ----
        const float4* ap = (const float4*)(A + (size_t)(bm + r) * K + k0 + cg);
        const float4* bp = (const float4*)(B + (size_t)(bn + r) * K + k0 + cg);
#pragma unroll
        for (int t = 0; t < 4; t++) {
            float4 v = ap[t];
            uint4 w = make_uint4(f2tf(v.x), f2tf(v.y), f2tf(v.z), f2tf(v.w));
            *(uint4*)&As[r * LDS + cg + t * 4] = w;
        }
#pragma unroll
        for (int t = 0; t < 4; t++) {
            float4 v = bp[t];
            uint4 w = make_uint4(f2tf(v.x), f2tf(v.y), f2tf(v.z), f2tf(v.w));
            *(uint4*)&Bs[r * LDS + cg + t * 4] = w;
        }
        __syncthreads();

        // ---- compute: 4 k-steps of 8 ----
#pragma unroll
        for (int ks = 0; ks < BK; ks += 8) {
            unsigned afr[4][4], bfr[4][2];
#pragma unroll
            for (int mf = 0; mf < 4; mf++) {
                const int base = (wm0 + mf * 16 + gr) * LDS + ks + gc;
                afr[mf][0] = As[base];
                afr[mf][1] = As[base + 8 * LDS];
                afr[mf][2] = As[base + 4];
                afr[mf][3] = As[base + 8 * LDS + 4];
            }
#pragma unroll
            for (int nf = 0; nf < 4; nf++) {
                const int base = (wn0 + nf * 8 + gr) * LDS + ks + gc;
                bfr[nf][0] = Bs[base];
                bfr[nf][1] = Bs[base + 4];
            }
#pragma unroll
            for (int mf = 0; mf < 4; mf++)
#pragma unroll
                for (int nf = 0; nf < 4; nf++)
                    mma_tf32(acc[mf][nf], afr[mf], bfr[nf]);
        }
        __syncthreads();
    }

    // ---- epilogue ----
#pragma unroll
    for (int mf = 0; mf < 4; mf++) {
#pragma unroll
        for (int nf = 0; nf < 4; nf++) {
            const int row = bm + wm0 + mf * 16 + gr;     // and row+8
            const int col = bn + wn0 + nf * 8 + 2 * gc;  // and col+1
            float* c = acc[mf][nf];

            if (MODE == 0) {
                float bx = bias[col], by = bias[col + 1];
                float2 v0 = make_float2(c[0] + bx, c[1] + by);
                float2 v1 = make_float2(c[2] + bx, c[3] + by);
                *(float2*)(Cg + (size_t)row * N + col)       = v0;
                *(float2*)(Cg + (size_t)(row + 8) * N + col) = v1;
            } else if (MODE == 1) {
                // transposed: Vt[b][e=col][s], b/s from global token index
                float bx = bias[col], by = bias[col + 1];
                const int b0 = row >> 11, s0 = row & 2047;
                const int b1 = (row + 8) >> 11, s1 = (row + 8) & 2047;
                Cg[(size_t)b0 * SEQ * EMB + (size_t)col * SEQ + s0]       = c[0] + bx;
                Cg[(size_t)b0 * SEQ * EMB + (size_t)(col + 1) * SEQ + s0] = c[1] + by;
                Cg[(size_t)b1 * SEQ * EMB + (size_t)col * SEQ + s1]       = c[2] + bx;
                Cg[(size_t)b1 * SEQ * EMB + (size_t)(col + 1) * SEQ + s1] = c[3] + by;
            } else if (MODE == 2) {
                float* C = Cg + (size_t)b * M * N;
                float2 v0 = make_float2(c[0] * scale, c[1] * scale);
                float2 v1 = make_float2(c[2] * scale, c[3] * scale);
                *(float2*)(C + (size_t)row * N + col)       = v0;
                *(float2*)(C + (size_t)(row + 8) * N + col) = v1;
            } else {
                float* C = Cg + (size_t)b * M * N;
                float2 v0 = make_float2(c[0], c[1]);
                float2 v1 = make_float2(c[2], c[3]);
                *(float2*)(C + (size_t)row * N + col)       = v0;
                *(float2*)(C + (size_t)(row + 8) * N + col) = v1;
            }
        }
    }
}

// =====================================================================
// Causal softmax in place on P. One CTA (256 thr) per row.
// Reads only j <= i; writes zeros for j > i (so PV needs no mask).
// =====================================================================
__global__ __launch_bounds__(256) void softmax_causal(float* __restrict__ Pg)
{
    const int i = blockIdx.x;
    const int b = blockIdx.y;
    float* row = Pg + ((size_t)b * SEQ + i) * SEQ;
    const int len = i + 1;

    __shared__ float buf[SEQ];
    __shared__ float red[8];
    __shared__ float sval;

    const int tid = threadIdx.x;
    const int lane = tid & 31;
    const int warp = tid >> 5;

    float m = -1e30f;
    for (int j = tid; j < len; j += 256) {
        float v = row[j];
        buf[j] = v;
        m = fmaxf(m, v);
    }
#pragma unroll
    for (int o = 16; o > 0; o >>= 1) m = fmaxf(m, __shfl_xor_sync(0xffffffffu, m, o));
    if (lane == 0) red[warp] = m;
    __syncthreads();
    if (tid == 0) {
        float mm = red[0];
#pragma unroll
        for (int w = 1; w < 8; w++) mm = fmaxf(mm, red[w]);
        sval = mm;
    }
    __syncthreads();
    const float rowmax = sval;
    __syncthreads();

    float s = 0.0f;
    for (int j = tid; j < len; j += 256) {
        float e = __expf(buf[j] - rowmax);
        buf[j] = e;
        s += e;
    }
#pragma unroll
    for (int o = 16; o > 0; o >>= 1) s += __shfl_xor_sync(0xffffffffu, s, o);
    if (lane == 0) red[warp] = s;
    __syncthreads();
    if (tid == 0) {
        float ss = red[0];
#pragma unroll
        for (int w = 1; w < 8; w++) ss += red[w];
        sval = 1.0f / ss;
    }
    __syncthreads();
    const float inv = sval;

    for (int j = tid; j < len; j += 256) row[j] = buf[j] * inv;
    for (int j = len + tid; j < SEQ; j += 256) row[j] = 0.0f;
}

// =====================================================================
// launch
// =====================================================================
extern "C" void kernel_launch(void* const* d_in, const int* in_sizes, int n_in,
                              void* d_out, int out_size)
{
    const float* x  = (const float*)d_in[0];
    const float* Wq = (const float*)d_in[1];
    const float* bq = (const float*)d_in[2];
    const float* Wk = (const float*)d_in[3];
    const float* bk = (const float*)d_in[4];
    const float* Wv = (const float*)d_in[5];
    const float* bv = (const float*)d_in[6];
    float* out = (float*)d_out;

    float* q; cudaGetSymbolAddress((void**)&q, g_q);
    float* k; cudaGetSymbolAddress((void**)&k, g_k);
    float* v; cudaGetSymbolAddress((void**)&v, g_v);
    float* p; cudaGetSymbolAddress((void**)&p, g_p);

    // 1) QKV projections (V written transposed per batch: Vt[b][e][s])
    dim3 gProj(EMB / 128, MTOT / 128, 1);
    mma_gemm<0><<<gProj, 256>>>(x, Wq, bq, q, MTOT, EMB, EMB, 1.0f);
    mma_gemm<0><<<gProj, 256>>>(x, Wk, bk, k, MTOT, EMB, EMB, 1.0f);
    mma_gemm<1><<<gProj, 256>>>(x, Wv, bv, v, MTOT, EMB, EMB, 1.0f);

    // 2) scaled QK^T with causal block skipping
    const float scale = 1.0f / 32.0f;  // 1/sqrt(1024)
    dim3 gQK(SEQ / 128, SEQ / 128, BATCH);
    mma_gemm<2><<<gQK, 256>>>(q, k, nullptr, p, SEQ, SEQ, EMB, scale);

    // 3) causal softmax (writes zeros above diagonal)
    dim3 gSM(SEQ, BATCH, 1);
    softmax_causal<<<gSM, 256>>>(p);

    // 4) PV: O = P * Vt^T (k-loop truncated at diagonal)
    dim3 gPV(EMB / 128, SEQ / 128, BATCH);
    mma_gemm<3><<<gPV, 256>>>(p, v, nullptr, out, SEQ, EMB, SEQ, 1.0f);
}

// round 4
// speedup vs baseline: 4.3611x; 1.1229x over previous
#include <cuda_runtime.h>
#include <cstdint>
#include <cstddef>

#define BATCH 8
#define SEQ   2048
#define EMB   1024
#define MTOT  (BATCH * SEQ)

// ---------------- scratch (device globals; no runtime allocation) ----------------
__device__ float g_q[(size_t)MTOT * EMB];          // Q (tf32-rounded)
__device__ float g_k[(size_t)MTOT * EMB];          // K (tf32-rounded)
__device__ float g_v[(size_t)MTOT * EMB];          // Vt [b][e][s] (tf32-rounded)
__device__ float g_p[(size_t)BATCH * SEQ * SEQ];   // scores / probs
__device__ float g_xr[(size_t)MTOT * EMB];         // x rounded to tf32
__device__ float g_wr[(size_t)3 * EMB * EMB];      // Wq,Wk,Wv rounded to tf32

// ---------------- helpers ----------------
__device__ __forceinline__ unsigned f2tf(float f) {
    unsigned u;
    asm("cvt.rna.tf32.f32 %0, %1;" : "=r"(u) : "f"(f));
    return u;
}

__device__ __forceinline__ void mma_tf32(float c[4], const unsigned a[4], const unsigned b[2]) {
    asm volatile(
        "mma.sync.aligned.m16n8k8.row.col.f32.tf32.tf32.f32 "
        "{%0,%1,%2,%3}, {%4,%5,%6,%7}, {%8,%9}, {%0,%1,%2,%3};\n"
        : "+f"(c[0]), "+f"(c[1]), "+f"(c[2]), "+f"(c[3])
        : "r"(a[0]), "r"(a[1]), "r"(a[2]), "r"(a[3]), "r"(b[0]), "r"(b[1]));
}

// XOR swizzle: conflict-free vector loads, <=2-way stores
__device__ __forceinline__ int swz(int lane, int kb) {
    return lane ^ ((lane >> 3) & 3) ^ (kb & 1) ^ ((kb & 2) << 1);
}

// =====================================================================
// HMMA tf32 NT GEMM: C[m,n] = sum_k A[m,k]*B[n,k]
//   tile 128x128, BK=16, 256 thr, 8 warps of 64x32, fragment-native smem.
//   MODE 0: proj, C row-major, +bias, round->tf32
//   MODE 1: proj, C -> Vt[b][n][s] transposed, +bias, round->tf32
//   MODE 2: QK^T per batch, *scale, causal tile skip
//   MODE 3: PV per batch, k truncated at diagonal
// Smem word layouts (per 16-k chunk, per buffer 2048 words each):
//   A: ((mt*2+kb)*32 + swz(lane,kb))*4 + t,  mt=m>>4, lane=(m&7)*4+(k&3),
//      t = ((m>>3)&1) | (((k>>2)&1)<<1)           -> LDS.128 = one a-frag
//   B: ((nt*2+kb)*32 + swz(lane,kb))*4 + t,  nt=n>>4, lane=(n&7)*4+(k&3),
//      t = ((k>>2)&1) | (((n>>3)&1)<<1)           -> LDS.128 = two b-frags
// =====================================================================
template <int MODE>
__global__ __launch_bounds__(256, 2) void mma_gemm(
    const float* __restrict__ Ag,
    const float* __restrict__ Bg,
    const float* __restrict__ bias,
    float* __restrict__ Cg,
    int M, int N, int K, float scale)
{
    constexpr int BM = 128, BK = 16;
    __shared__ __align__(16) float As[2][2048];
    __shared__ __align__(16) float Bs[2][2048];

    const int bm = blockIdx.y * BM;
    const int bn = blockIdx.x * BM;
    if (MODE == 2 && blockIdx.x > blockIdx.y) return;  // fully masked tile

    const int b = (MODE >= 2) ? blockIdx.z : 0;
    const float* A = Ag + (size_t)b * M * K;
    const float* B = Bg + (size_t)b * N * K;

    const int tid  = threadIdx.x;
    const int lane = tid & 31;
    const int wid  = tid >> 5;
    const int gr   = lane >> 2;
    const int gc   = lane & 3;
    const int wm0  = (wid >> 2) * 64;
    const int wn0  = (wid & 3) * 32;
    const int mtb  = (wid >> 2) * 4;   // A 16-row block base
    const int ntb  = (wid & 3) * 2;    // B 16-col block base

    // G2S: thread -> row r, k-half kh (8 floats = 2 float4)
    const int r  = tid >> 1;
    const int kh = tid & 1;

    float acc[4][4][4];
#pragma unroll
    for (int i = 0; i < 4; i++)
#pragma unroll
        for (int j = 0; j < 4; j++)
#pragma unroll
            for (int t = 0; t < 4; t++) acc[i][j][t] = 0.0f;

    const int kend = (MODE == 3) ? (bm + BM) : K;
    const int nch  = kend >> 4;

    float4 pa0, pa1, pb0, pb1;   // prefetch regs

    auto ldg = [&](int c) {
        const float* ap = A + (size_t)(bm + r) * K + (c << 4) + kh * 8;
        const float* bp = B + (size_t)(bn + r) * K + (c << 4) + kh * 8;
        pa0 = *(const float4*)(ap);
        pa1 = *(const float4*)(ap + 4);
        pb0 = *(const float4*)(bp);
        pb1 = *(const float4*)(bp + 4);
    };

    auto sts = [&](int buf) {
        float av[8] = {pa0.x, pa0.y, pa0.z, pa0.w, pa1.x, pa1.y, pa1.z, pa1.w};
        float bv[8] = {pb0.x, pb0.y, pb0.z, pb0.w, pb1.x, pb1.y, pb1.z, pb1.w};
        const int mt = r >> 4;
#pragma unroll
        for (int s = 0; s < 8; s++) {
            const int ln = ((r & 7) << 2) | (s & 3);
            const int sw = swz(ln, kh);
            const int ta = ((r >> 3) & 1) | (((s >> 2) & 1) << 1);
            const int tb = ((s >> 2) & 1) | (((r >> 3) & 1) << 1);
            As[buf][(((mt * 2 + kh) << 5) + sw) * 4 + ta] = av[s];
            Bs[buf][(((mt * 2 + kh) << 5) + sw) * 4 + tb] = bv[s];
        }
    };

    ldg(0);
    sts(0);

    for (int i = 0; i < nch; i++) {
        __syncthreads();                 // buf i&1 ready for all
        if (i + 1 < nch) ldg(i + 1);     // overlap gmem with compute

        const int buf = i & 1;
#pragma unroll
        for (int kb = 0; kb < 2; kb++) {
            const int sw = swz(lane, kb);
            unsigned afr[4][4], bfr[4][2];
#pragma unroll
            for (int mf = 0; mf < 4; mf++) {
                uint4 q = *(const uint4*)&As[buf][((((mtb + mf) * 2 + kb) << 5) + sw) * 4];
                afr[mf][0] = q.x; afr[mf][1] = q.y; afr[mf][2] = q.z; afr[mf][3] = q.w;
            }
#pragma unroll
            for (int h = 0; h < 2; h++) {
                uint4 q = *(const uint4*)&Bs[buf][((((ntb + h) * 2 + kb) << 5) + sw) * 4];
                bfr[2 * h][0] = q.x; bfr[2 * h][1] = q.y;
                bfr[2 * h + 1][0] = q.z; bfr[2 * h + 1][1] = q.w;
            }
#pragma unroll
            for (int mf = 0; mf < 4; mf++)
#pragma unroll
                for (int nf = 0; nf < 4; nf++)
                    mma_tf32(acc[mf][nf], afr[mf], bfr[nf]);
        }

        if (i + 1 < nch) sts((i + 1) & 1);   // disjoint from buf being read
    }

    // ---- epilogue ----
#pragma unroll
    for (int mf = 0; mf < 4; mf++) {
#pragma unroll
        for (int nf = 0; nf < 4; nf++) {
            const int row = bm + wm0 + mf * 16 + gr;
            const int col = bn + wn0 + nf * 8 + 2 * gc;
            float* c = acc[mf][nf];

            if (MODE == 0) {
                float bx = bias[col], by = bias[col + 1];
                float2 v0 = make_float2(__uint_as_float(f2tf(c[0] + bx)),
                                        __uint_as_float(f2tf(c[1] + by)));
                float2 v1 = make_float2(__uint_as_float(f2tf(c[2] + bx)),
                                        __uint_as_float(f2tf(c[3] + by)));
                *(float2*)(Cg + (size_t)row * N + col)       = v0;
                *(float2*)(Cg + (size_t)(row + 8) * N + col) = v1;
            } else if (MODE == 1) {
                float bx = bias[col], by = bias[col + 1];
                const int b0 = row >> 11, s0 = row & (SEQ - 1);
                const int b1 = (row + 8) >> 11, s1 = (row + 8) & (SEQ - 1);
                Cg[(size_t)b0 * EMB * SEQ + (size_t)col * SEQ + s0]       = __uint_as_float(f2tf(c[0] + bx));
                Cg[(size_t)b0 * EMB * SEQ + (size_t)(col + 1) * SEQ + s0] = __uint_as_float(f2tf(c[1] + by));
                Cg[(size_t)b1 * EMB * SEQ + (size_t)col * SEQ + s1]       = __uint_as_float(f2tf(c[2] + bx));
                Cg[(size_t)b1 * EMB * SEQ + (size_t)(col + 1) * SEQ + s1] = __uint_as_float(f2tf(c[3] + by));
            } else if (MODE == 2) {
                float* C = Cg + (size_t)b * M * N;
                float2 v0 = make_float2(c[0] * scale, c[1] * scale);
                float2 v1 = make_float2(c[2] * scale, c[3] * scale);
                *(float2*)(C + (size_t)row * N + col)       = v0;
                *(float2*)(C + (size_t)(row + 8) * N + col) = v1;
            } else {
                float* C = Cg + (size_t)b * M * N;
                float2 v0 = make_float2(c[0], c[1]);
                float2 v1 = make_float2(c[2], c[3]);
                *(float2*)(C + (size_t)row * N + col)       = v0;
                *(float2*)(C + (size_t)(row + 8) * N + col) = v1;
            }
        }
    }
}

// =====================================================================
// elementwise tf32-rna rounding
// =====================================================================
__global__ __launch_bounds__(256) void round_tf32(const float* __restrict__ in,
                                                  float* __restrict__ out, int n4)
{
    int i = blockIdx.x * blockDim.x + threadIdx.x;
    if (i < n4) {
        float4 v = ((const float4*)in)[i];
        float4 o;
        o.x = __uint_as_float(f2tf(v.x));
        o.y = __uint_as_float(f2tf(v.y));
        o.z = __uint_as_float(f2tf(v.z));
        o.w = __uint_as_float(f2tf(v.w));
        ((float4*)out)[i] = o;
    }
}

// =====================================================================
// Causal softmax in place. One CTA (256 thr) per row.
// Writes tf32-rounded probs for j<=i, zeros for j>i.
// =====================================================================
__global__ __launch_bounds__(256) void softmax_causal(float* __restrict__ Pg)
{
    const int i = blockIdx.x;
    const int b = blockIdx.y;
    float* row = Pg + ((size_t)b * SEQ + i) * SEQ;
    const int len = i + 1;

    __shared__ float buf[SEQ];
    __shared__ float red[8];
    __shared__ float sval;

    const int tid = threadIdx.x;
    const int lane = tid & 31;
    const int warp = tid >> 5;

    float m = -1e30f;
    for (int j = tid; j < len; j += 256) {
        float v = row[j];
        buf[j] = v;
        m = fmaxf(m, v);
    }
#pragma unroll
    for (int o = 16; o > 0; o >>= 1) m = fmaxf(m, __shfl_xor_sync(0xffffffffu, m, o));
    if (lane == 0) red[warp] = m;
    __syncthreads();
    if (tid == 0) {
        float mm = red[0];
#pragma unroll
        for (int w = 1; w < 8; w++) mm = fmaxf(mm, red[w]);
        sval = mm;
    }
    __syncthreads();
    const float rowmax = sval;
    __syncthreads();

    float s = 0.0f;
    for (int j = tid; j < len; j += 256) {
        float e = __expf(buf[j] - rowmax);
        buf[j] = e;
        s += e;
    }
#pragma unroll
    for (int o = 16; o > 0; o >>= 1) s += __shfl_xor_sync(0xffffffffu, s, o);
    if (lane == 0) red[warp] = s;
    __syncthreads();
    if (tid == 0) {
        float ss = red[0];
#pragma unroll
        for (int w = 1; w < 8; w++) ss += red[w];
        sval = 1.0f / ss;
    }
    __syncthreads();
    const float inv = sval;

    for (int j = tid; j < len; j += 256) row[j] = __uint_as_float(f2tf(buf[j] * inv));
    for (int j = len + tid; j < SEQ; j += 256) row[j] = 0.0f;
}

// =====================================================================
// launch
// =====================================================================
extern "C" void kernel_launch(void* const* d_in, const int* in_sizes, int n_in,
                              void* d_out, int out_size)
{
    const float* x  = (const float*)d_in[0];
    const float* Wq = (const float*)d_in[1];
    const float* bq = (const float*)d_in[2];
    const float* Wk = (const float*)d_in[3];
    const float* bk = (const float*)d_in[4];
    const float* Wv = (const float*)d_in[5];
    const float* bv = (const float*)d_in[6];
    float* out = (float*)d_out;

    float* q;  cudaGetSymbolAddress((void**)&q,  g_q);
    float* k;  cudaGetSymbolAddress((void**)&k,  g_k);
    float* v;  cudaGetSymbolAddress((void**)&v,  g_v);
    float* p;  cudaGetSymbolAddress((void**)&p,  g_p);
    float* xr; cudaGetSymbolAddress((void**)&xr, g_xr);
    float* wr; cudaGetSymbolAddress((void**)&wr, g_wr);

    // 0) pre-round x and weights to tf32 (rna) -> no cvt in GEMM hot loops
    {
        int n4x = MTOT * EMB / 4;
        round_tf32<<<(n4x + 255) / 256, 256>>>(x, xr, n4x);
        int n4w = EMB * EMB / 4;
        round_tf32<<<(n4w + 255) / 256, 256>>>(Wq, wr + (size_t)0 * EMB * EMB, n4w);
        round_tf32<<<(n4w + 255) / 256, 256>>>(Wk, wr + (size_t)1 * EMB * EMB, n4w);
        round_tf32<<<(n4w + 255) / 256, 256>>>(Wv, wr + (size_t)2 * EMB * EMB, n4w);
    }

    // 1) QKV projections (V transposed -> Vt[b][e][s])
    dim3 gProj(EMB / 128, MTOT / 128, 1);
    mma_gemm<0><<<gProj, 256>>>(xr, wr + (size_t)0 * EMB * EMB, bq, q, MTOT, EMB, EMB, 1.0f);
    mma_gemm<0><<<gProj, 256>>>(xr, wr + (size_t)1 * EMB * EMB, bk, k, MTOT, EMB, EMB, 1.0f);
    mma_gemm<1><<<gProj, 256>>>(xr, wr + (size_t)2 * EMB * EMB, bv, v, MTOT, EMB, EMB, 1.0f);

    // 2) scaled QK^T with causal tile skip (garbage above diagonal, never read)
    dim3 gQK(SEQ / 128, SEQ / 128, BATCH);
    mma_gemm<2><<<gQK, 256>>>(q, k, nullptr, p, SEQ, SEQ, EMB, 1.0f / 32.0f);

    // 3) causal softmax (rounds probs to tf32, zeros above diagonal)
    dim3 gSM(SEQ, BATCH, 1);
    softmax_causal<<<gSM, 256>>>(p);

    // 4) PV: O = P * Vt^T, k truncated at diagonal
    dim3 gPV(EMB / 128, SEQ / 128, BATCH);
    mma_gemm<3><<<gPV, 256>>>(p, v, nullptr, out, SEQ, EMB, SEQ, 1.0f);
}